// round 6
// baseline (speedup 1.0000x reference)
#include <cuda_runtime.h>
#include <cstdint>

// Problem constants
#define BB 16
#define SS 64
#define TT_ 4096
#define CC 512
#define HH 8
#define DD 64

#define TSTR 20      // seg tile row stride (floats): 80B rows, cp.async 16B aligned,
                     // LDS.128 at 80B lane stride is bank-conflict-free
#define MEGA 128     // t-positions of probabilities staged per outer iteration
#define SEG_CH 256   // channels per seg block (channel split x2)
#define SEG_SMEM ((2 * SEG_CH * TSTR + MEGA * HH) * 4)   // 45056 B

#define CSPLIT 4     // att channel split
#define CCH (CC / CSPLIT)   // 128 channels per att block

// Scratch (device globals: allocation-free rule)
__device__ float g_q[CC];
__device__ float g_w[HH * CC];
__device__ float g_cb[CC];
__device__ float g_att[BB * HH * TT_];               // 2 MB
__device__ float g_m[(size_t)BB * SS * HH * CC];     // 16 MB
__device__ float g_tmp[BB * SS * CC];                // 2 MB

__device__ __forceinline__ float warp_red_max(float v) {
#pragma unroll
    for (int o = 16; o; o >>= 1) v = fmaxf(v, __shfl_xor_sync(0xffffffffu, v, o));
    return v;
}
__device__ __forceinline__ float warp_red_sum(float v) {
#pragma unroll
    for (int o = 16; o; o >>= 1) v += __shfl_xor_sync(0xffffffffu, v, o);
    return v;
}

// ---------------------------------------------------------------------------
// Setup stage 1: q = Wq@x + bq ; cb = bp + Wp@bv. grid 32 x 512.
// ---------------------------------------------------------------------------
__global__ void setup1_kernel(const float* __restrict__ x, const float* __restrict__ Wq,
                              const float* __restrict__ bq, const float* __restrict__ Wp,
                              const float* __restrict__ bv, const float* __restrict__ bp) {
    __shared__ float xs[CC], bvs[CC];
    int tid = threadIdx.x, lane = tid & 31, wid = tid >> 5;
    xs[tid] = x[tid];
    bvs[tid] = bv[tid];
    __syncthreads();

    int o = blockIdx.x * 16 + wid;
    {
        const float* r = Wq + (size_t)o * CC;
        float s = 0.f;
#pragma unroll 4
        for (int c = lane; c < CC; c += 32) s += r[c] * xs[c];
        s = warp_red_sum(s);
        if (lane == 0) g_q[o] = s + bq[o];
    }
    {
        const float* r = Wp + (size_t)o * CC;
        float s = 0.f;
#pragma unroll 4
        for (int c = lane; c < CC; c += 32) s += r[c] * bvs[c];
        s = warp_red_sum(s);
        if (lane == 0) g_cb[o] = s + bp[o];
    }
}

// ---------------------------------------------------------------------------
// Setup stage 2: w[h,c] = (1/8) * sum_d q[h*64+d] * Wk[h*64+d, c].  grid 8 x 512.
// ---------------------------------------------------------------------------
__global__ void setup2_kernel(const float* __restrict__ Wk) {
    __shared__ float qh[DD];
    int h = blockIdx.x, tid = threadIdx.x;
    if (tid < DD) qh[tid] = g_q[h * DD + tid];
    __syncthreads();
    const float* base = Wk + (size_t)h * DD * CC + tid;
    float s = 0.f;
#pragma unroll 8
    for (int d = 0; d < DD; d++) s = fmaf(qh[d], base[(size_t)d * CC], s);
    g_w[h * CC + tid] = 0.125f * s;
}

// ---------------------------------------------------------------------------
// Init: zero g_att + g_tmp (atomic targets), out = broadcast bias cb.
// grid 2048 x 256 -> 524288 threads. g_att is 524288 floats (1 each),
// g_tmp 524288 (1 each), out 524288 (1 each).
// ---------------------------------------------------------------------------
__global__ void init_kernel(float* __restrict__ out) {
    int idx = blockIdx.x * 256 + threadIdx.x;
    g_tmp[idx] = 0.f;
    out[idx] = g_cb[idx & (CC - 1)];
    g_att[idx] = 0.f;
}

// ---------------------------------------------------------------------------
// att v3: att[b,h,t] += w[h, cs:cs+128] . eh[b, cs:cs+128, t], 2 t per thread.
// grid (T/512, B, CSPLIT) = 512 blocks x 256 threads.
// ---------------------------------------------------------------------------
__global__ void att_kernel(const float* __restrict__ eh) {
    __shared__ float ws[CCH][HH];  // [c][h], 4 KB
    int tid = threadIdx.x;
    int b = blockIdx.y;
    int cs = blockIdx.z * CCH;
    for (int idx = tid; idx < CCH * HH; idx += 256) {
        int c = idx >> 3, h = idx & 7;
        ws[c][h] = g_w[h * CC + cs + c];
    }
    __syncthreads();

    int t = blockIdx.x * 512 + tid * 2;
    const float* e = eh + (size_t)b * CC * TT_ + (size_t)cs * TT_ + t;
    float acc[HH][2];
#pragma unroll
    for (int h = 0; h < HH; h++) { acc[h][0] = 0.f; acc[h][1] = 0.f; }

#pragma unroll 8
    for (int c = 0; c < CCH; c++) {
        float2 v = *(const float2*)&e[(size_t)c * TT_];
        float4 w0 = *(const float4*)&ws[c][0];
        float4 w1 = *(const float4*)&ws[c][4];
        acc[0][0] = fmaf(w0.x, v.x, acc[0][0]); acc[0][1] = fmaf(w0.x, v.y, acc[0][1]);
        acc[1][0] = fmaf(w0.y, v.x, acc[1][0]); acc[1][1] = fmaf(w0.y, v.y, acc[1][1]);
        acc[2][0] = fmaf(w0.z, v.x, acc[2][0]); acc[2][1] = fmaf(w0.z, v.y, acc[2][1]);
        acc[3][0] = fmaf(w0.w, v.x, acc[3][0]); acc[3][1] = fmaf(w0.w, v.y, acc[3][1]);
        acc[4][0] = fmaf(w1.x, v.x, acc[4][0]); acc[4][1] = fmaf(w1.x, v.y, acc[4][1]);
        acc[5][0] = fmaf(w1.y, v.x, acc[5][0]); acc[5][1] = fmaf(w1.y, v.y, acc[5][1]);
        acc[6][0] = fmaf(w1.z, v.x, acc[6][0]); acc[6][1] = fmaf(w1.z, v.y, acc[6][1]);
        acc[7][0] = fmaf(w1.w, v.x, acc[7][0]); acc[7][1] = fmaf(w1.w, v.y, acc[7][1]);
    }
    float* ao = g_att + (size_t)b * HH * TT_ + t;
#pragma unroll
    for (int h = 0; h < HH; h++) {
        atomicAdd(&ao[(size_t)h * TT_], acc[h][0]);
        atomicAdd(&ao[(size_t)h * TT_ + 1], acc[h][1]);
    }
}

// ---------------------------------------------------------------------------
// seg v3: per (b,s, chalf) softmax (stats duplicated per chalf) then
// m[h, cs+c] = sum_t p[h,t]*eh[cs+c,t].  grid (B*S, 2) x 256 threads.
// 256 channels per block -> 44 KB smem -> ~5 blocks/SM. Thread owns 1 channel.
// ---------------------------------------------------------------------------
__device__ __forceinline__ void seg_prefetch(float* dst, const float* __restrict__ ebase,
                                             int t0, int tid) {
#pragma unroll
    for (int k = 0; k < 4; k++) {
        int idx = tid + k * 256;          // 0..1023
        int row = idx >> 2;               // channel 0..255
        int s16 = (idx & 3) * 4;          // float offset of 16B piece
        const float* src = ebase + (size_t)row * TT_ + t0 + s16;
        uint32_t sa = (uint32_t)__cvta_generic_to_shared(dst + row * TSTR + s16);
        asm volatile("cp.async.cg.shared.global [%0], [%1], 16;\n" ::"r"(sa), "l"(src)
                     : "memory");
    }
}

extern __shared__ float dyn_smem[];

__global__ void seg_kernel(const float* __restrict__ eh, const int* __restrict__ ss,
                           const int* __restrict__ se) {
    float* tile0 = dyn_smem;                     // 256*20 floats
    float* tile1 = dyn_smem + SEG_CH * TSTR;     // 256*20 floats
    float* ps = dyn_smem + 2 * SEG_CH * TSTR;    // 128*8 floats, [j][h]
    __shared__ float smax[HH], sinv[HH];
    __shared__ float wred[8][HH];

    int bid = blockIdx.x;
    int b = bid >> 6;
    int cs = blockIdx.y * SEG_CH;
    int st = ss[bid], en = se[bid];
    int tid = threadIdx.x, lane = tid & 31, wid = tid >> 5;
    const float* ebase = eh + (size_t)b * CC * TT_ + (size_t)cs * TT_;
    const float* abase = g_att + (size_t)b * HH * TT_;

    // phase 1: per-head max
    float mx[HH];
#pragma unroll
    for (int h = 0; h < HH; h++) mx[h] = -3.0e38f;
    for (int t = st + tid; t < en; t += 256) {
#pragma unroll
        for (int h = 0; h < HH; h++) mx[h] = fmaxf(mx[h], abase[(size_t)h * TT_ + t]);
    }
#pragma unroll
    for (int h = 0; h < HH; h++) mx[h] = warp_red_max(mx[h]);
    if (lane == 0)
        for (int h = 0; h < HH; h++) wred[wid][h] = mx[h];
    __syncthreads();
    if (tid < HH) {
        float v = wred[0][tid];
        for (int w = 1; w < 8; w++) v = fmaxf(v, wred[w][tid]);
        smax[tid] = v;
    }
    __syncthreads();

    // phase 2: per-head sum of exp
    float sm[HH];
#pragma unroll
    for (int h = 0; h < HH; h++) sm[h] = 0.f;
    for (int t = st + tid; t < en; t += 256) {
#pragma unroll
        for (int h = 0; h < HH; h++) sm[h] += __expf(abase[(size_t)h * TT_ + t] - smax[h]);
    }
#pragma unroll
    for (int h = 0; h < HH; h++) sm[h] = warp_red_sum(sm[h]);
    if (lane == 0)
        for (int h = 0; h < HH; h++) wred[wid][h] = sm[h];
    __syncthreads();
    if (tid < HH) {
        float v = 0.f;
        for (int w = 0; w < 8; w++) v += wred[w][tid];
        sinv[tid] = 1.f / v;
    }
    __syncthreads();

    // phase 3: thread owns channel c = cs + tid
    float acc[HH];
#pragma unroll
    for (int h = 0; h < HH; h++) acc[h] = 0.f;

    int t_lo = st & ~15;
    for (int mega = t_lo; mega < en; mega += MEGA) {
        // stage probabilities for this mega-chunk: ps[j*8+h], 1024 entries
#pragma unroll
        for (int k = 0; k < 4; k++) {
            int idx = tid + k * 256;
            int j = idx >> 3, h = idx & 7;
            int t = mega + j;
            float v = 0.f;
            if (t >= st && t < en)
                v = __expf(abase[(size_t)h * TT_ + t] - smax[h]) * sinv[h];
            ps[idx] = v;
        }
        __syncthreads();

        int mend = min(mega + MEGA, en);
        int nch = (mend - mega + 15) >> 4;

        seg_prefetch(tile0, ebase, mega, tid);
        asm volatile("cp.async.commit_group;\n" ::: "memory");

        for (int ci = 0; ci < nch; ci++) {
            float* tb = (ci & 1) ? tile1 : tile0;
            float* tn = (ci & 1) ? tile0 : tile1;
            bool more = (ci + 1 < nch);
            if (more) {
                seg_prefetch(tn, ebase, mega + (ci + 1) * 16, tid);
                asm volatile("cp.async.commit_group;\n" ::: "memory");
                asm volatile("cp.async.wait_group 1;\n" ::: "memory");
            } else {
                asm volatile("cp.async.wait_group 0;\n" ::: "memory");
            }
            __syncthreads();

            const float* pj = ps + ci * 16 * 8;
            const float* r0 = tb + tid * TSTR;
#pragma unroll
            for (int jg = 0; jg < 4; jg++) {
                float4 e0 = *(const float4*)(r0 + jg * 4);
                float ea[4] = {e0.x, e0.y, e0.z, e0.w};
#pragma unroll
                for (int jj = 0; jj < 4; jj++) {
                    float4 pA = *(const float4*)(pj + (jg * 4 + jj) * 8);
                    float4 pB = *(const float4*)(pj + (jg * 4 + jj) * 8 + 4);
                    float p[8] = {pA.x, pA.y, pA.z, pA.w, pB.x, pB.y, pB.z, pB.w};
#pragma unroll
                    for (int h = 0; h < HH; h++) acc[h] = fmaf(p[h], ea[jj], acc[h]);
                }
            }
            __syncthreads();  // compute done before this buffer is refilled
        }
    }

    float* mo = g_m + (size_t)bid * HH * CC + cs + tid;
#pragma unroll
    for (int h = 0; h < HH; h++) mo[h * CC] = acc[h];
}

// ---------------------------------------------------------------------------
// fp32 tiled GEMM, 64x64 tile, split-K via [kbeg,kend), atomicAdd epilogue.
// C[m,n] += sum_k A[m,k]*B[n,k]. 256 threads, 4x4 micro.
// ---------------------------------------------------------------------------
__device__ __forceinline__ void gemm_body(const float* __restrict__ A,
                                          const float* __restrict__ Bm,
                                          float* __restrict__ Cm,
                                          int lda, int ldb, int ldc, int kbeg, int kend) {
    __shared__ float As[32][68];
    __shared__ float Bs[32][68];
    int tid = threadIdx.x;
    int tx = tid & 15, ty = tid >> 4;
    int m0 = blockIdx.x * 64, n0 = blockIdx.y * 64;
    float acc[4][4];
#pragma unroll
    for (int i = 0; i < 4; i++)
#pragma unroll
        for (int j = 0; j < 4; j++) acc[i][j] = 0.f;

    for (int k0 = kbeg; k0 < kend; k0 += 32) {
#pragma unroll
        for (int i = 0; i < 8; i++) {
            int idx = tid + i * 256;
            int row = idx >> 5, col = idx & 31;
            As[col][row] = A[(size_t)(m0 + row) * lda + k0 + col];
            Bs[col][row] = Bm[(size_t)(n0 + row) * ldb + k0 + col];
        }
        __syncthreads();
#pragma unroll
        for (int kk = 0; kk < 32; kk++) {
            float4 a4 = *(const float4*)&As[kk][ty * 4];
            float4 b4 = *(const float4*)&Bs[kk][tx * 4];
            float a[4] = {a4.x, a4.y, a4.z, a4.w};
            float bb[4] = {b4.x, b4.y, b4.z, b4.w};
#pragma unroll
            for (int i = 0; i < 4; i++)
#pragma unroll
                for (int j = 0; j < 4; j++) acc[i][j] = fmaf(a[i], bb[j], acc[i][j]);
        }
        __syncthreads();
    }
#pragma unroll
    for (int i = 0; i < 4; i++) {
        int mm = m0 + ty * 4 + i;
#pragma unroll
        for (int j = 0; j < 4; j++) {
            int nn = n0 + tx * 4 + j;
            atomicAdd(&Cm[(size_t)mm * ldc + nn], acc[i][j]);
        }
    }
}

// D1: tmp[r, h*64+d] += sum_c m[r,h,c]*Wv[h*64+d,c].  grid (16,1,32): z = h*4 + ksplit
__global__ void gemm1_kernel(const float* __restrict__ Wv) {
    int h = blockIdx.z >> 2;
    int kb = (blockIdx.z & 3) * 128;
    gemm_body(g_m + h * CC, Wv + (size_t)h * DD * CC, g_tmp + h * DD,
              HH * CC, CC, CC, kb, kb + 128);
}

// D2: out[r,o] += sum_i tmp[r,i]*Wp[o,i].  grid (16, 8, 4)
__global__ void gemm2_kernel(const float* __restrict__ Wp, float* __restrict__ out) {
    int kb = blockIdx.z * 128;
    gemm_body(g_tmp, Wp, out, CC, CC, CC, kb, kb + 128);
}

// ---------------------------------------------------------------------------
extern "C" void kernel_launch(void* const* d_in, const int* in_sizes, int n_in,
                              void* d_out, int out_size) {
    const float* x  = (const float*)d_in[0];
    const float* eh = (const float*)d_in[1];
    const int*   st = (const int*)d_in[2];
    const int*   en = (const int*)d_in[3];
    const float* Wq = (const float*)d_in[4];
    const float* bq = (const float*)d_in[5];
    const float* Wk = (const float*)d_in[6];
    /* d_in[7] = bk: constant per head in logits, cancels in softmax */
    const float* Wv = (const float*)d_in[8];
    const float* bv = (const float*)d_in[9];
    const float* Wp = (const float*)d_in[10];
    const float* bp = (const float*)d_in[11];
    float* out = (float*)d_out;

    cudaFuncSetAttribute(seg_kernel, cudaFuncAttributeMaxDynamicSharedMemorySize,
                         SEG_SMEM);

    setup1_kernel<<<32, 512>>>(x, Wq, bq, Wp, bv, bp);
    setup2_kernel<<<HH, CC>>>(Wk);
    init_kernel<<<2048, 256>>>(out);
    att_kernel<<<dim3(TT_ / 512, BB, CSPLIT), 256>>>(eh);
    seg_kernel<<<dim3(BB * SS, 2), 256, SEG_SMEM>>>(eh, st, en);
    gemm1_kernel<<<dim3(16, 1, 32), 256>>>(Wv);
    gemm2_kernel<<<dim3(16, 8, 4), 256>>>(Wp, out);
}

// round 7
// speedup vs baseline: 1.1770x; 1.1770x over previous
#include <cuda_runtime.h>
#include <cstdint>

// Problem constants
#define BB 16
#define SS 64
#define TT_ 4096
#define CC 512
#define HH 8
#define DD 64

#define TSTR 20      // seg tile row stride (floats)
#define MEGA 128     // t-positions of probabilities staged per outer iteration
#define SEG_CH 256   // channels per seg block (channel split x2)
#define SEG_SMEM ((2 * SEG_CH * TSTR + MEGA * HH) * 4)   // 45056 B

#define CSPLIT 4     // att channel split
#define CCH (CC / CSPLIT)   // 128 channels per att block

#define GPAD 36      // gemm smem row stride: (36*r + c) % 32 = (4r+c)%32 -> conflict-free frags

// Scratch (device globals: allocation-free rule)
__device__ float g_q[CC];
__device__ float g_w[HH * CC];
__device__ float g_cb[CC];
__device__ float g_att[BB * HH * TT_];               // 2 MB
__device__ float g_m[(size_t)BB * SS * HH * CC];     // 16 MB
__device__ float g_tmp[BB * SS * CC];                // 2 MB

__device__ __forceinline__ float warp_red_max(float v) {
#pragma unroll
    for (int o = 16; o; o >>= 1) v = fmaxf(v, __shfl_xor_sync(0xffffffffu, v, o));
    return v;
}
__device__ __forceinline__ float warp_red_sum(float v) {
#pragma unroll
    for (int o = 16; o; o >>= 1) v += __shfl_xor_sync(0xffffffffu, v, o);
    return v;
}

// ---------------------------------------------------------------------------
// Setup stage 1: q = Wq@x + bq ; cb = bp + Wp@bv. grid 32 x 512.
// ---------------------------------------------------------------------------
__global__ void setup1_kernel(const float* __restrict__ x, const float* __restrict__ Wq,
                              const float* __restrict__ bq, const float* __restrict__ Wp,
                              const float* __restrict__ bv, const float* __restrict__ bp) {
    __shared__ float xs[CC], bvs[CC];
    int tid = threadIdx.x, lane = tid & 31, wid = tid >> 5;
    xs[tid] = x[tid];
    bvs[tid] = bv[tid];
    __syncthreads();

    int o = blockIdx.x * 16 + wid;
    {
        const float* r = Wq + (size_t)o * CC;
        float s = 0.f;
#pragma unroll 4
        for (int c = lane; c < CC; c += 32) s += r[c] * xs[c];
        s = warp_red_sum(s);
        if (lane == 0) g_q[o] = s + bq[o];
    }
    {
        const float* r = Wp + (size_t)o * CC;
        float s = 0.f;
#pragma unroll 4
        for (int c = lane; c < CC; c += 32) s += r[c] * bvs[c];
        s = warp_red_sum(s);
        if (lane == 0) g_cb[o] = s + bp[o];
    }
}

// ---------------------------------------------------------------------------
// Setup stage 2: w[h,c] = (1/8) * sum_d q[h*64+d] * Wk[h*64+d, c].  grid 8 x 512.
// ---------------------------------------------------------------------------
__global__ void setup2_kernel(const float* __restrict__ Wk) {
    __shared__ float qh[DD];
    int h = blockIdx.x, tid = threadIdx.x;
    if (tid < DD) qh[tid] = g_q[h * DD + tid];
    __syncthreads();
    const float* base = Wk + (size_t)h * DD * CC + tid;
    float s = 0.f;
#pragma unroll 8
    for (int d = 0; d < DD; d++) s = fmaf(qh[d], base[(size_t)d * CC], s);
    g_w[h * CC + tid] = 0.125f * s;
}

// ---------------------------------------------------------------------------
// Init: zero g_att (att atomic target). grid 512 x 256, float4 per thread.
// ---------------------------------------------------------------------------
__global__ void init_kernel() {
    int idx = blockIdx.x * 256 + threadIdx.x;
    ((float4*)g_att)[idx] = make_float4(0.f, 0.f, 0.f, 0.f);
}

// ---------------------------------------------------------------------------
// att (round-5 proven config): att[b,h,t] += w[h, cs:cs+128] . eh[b, cs:cs+128, t]
// grid (T/256, B, CSPLIT) = 1024 blocks x 256 threads, 1 t per thread.
// ---------------------------------------------------------------------------
__global__ void att_kernel(const float* __restrict__ eh) {
    __shared__ float ws[CCH][HH];  // [c][h], 4 KB
    int tid = threadIdx.x;
    int b = blockIdx.y;
    int cs = blockIdx.z * CCH;
    for (int idx = tid; idx < CCH * HH; idx += 256) {
        int c = idx >> 3, h = idx & 7;
        ws[c][h] = g_w[h * CC + cs + c];
    }
    __syncthreads();

    int t = blockIdx.x * 256 + tid;
    const float* e = eh + (size_t)b * CC * TT_ + (size_t)cs * TT_ + t;
    float acc[HH];
#pragma unroll
    for (int h = 0; h < HH; h++) acc[h] = 0.f;

#pragma unroll 8
    for (int c = 0; c < CCH; c++) {
        float v = e[(size_t)c * TT_];
        float4 w0 = *(const float4*)&ws[c][0];
        float4 w1 = *(const float4*)&ws[c][4];
        acc[0] = fmaf(w0.x, v, acc[0]);
        acc[1] = fmaf(w0.y, v, acc[1]);
        acc[2] = fmaf(w0.z, v, acc[2]);
        acc[3] = fmaf(w0.w, v, acc[3]);
        acc[4] = fmaf(w1.x, v, acc[4]);
        acc[5] = fmaf(w1.y, v, acc[5]);
        acc[6] = fmaf(w1.z, v, acc[6]);
        acc[7] = fmaf(w1.w, v, acc[7]);
    }
    float* ao = g_att + (size_t)b * HH * TT_ + t;
#pragma unroll
    for (int h = 0; h < HH; h++) atomicAdd(&ao[(size_t)h * TT_], acc[h]);
}

// ---------------------------------------------------------------------------
// seg: per (b,s,chalf) softmax then m[h, cs+c] = sum_t p[h,t]*eh[cs+c,t].
// grid (B*S, 2) x 256. cp.async double-buffered 256x16 tiles.
// ---------------------------------------------------------------------------
__device__ __forceinline__ void seg_prefetch(float* dst, const float* __restrict__ ebase,
                                             int t0, int tid) {
#pragma unroll
    for (int k = 0; k < 4; k++) {
        int idx = tid + k * 256;          // 0..1023
        int row = idx >> 2;               // channel 0..255
        int s16 = (idx & 3) * 4;          // float offset of 16B piece
        const float* src = ebase + (size_t)row * TT_ + t0 + s16;
        uint32_t sa = (uint32_t)__cvta_generic_to_shared(dst + row * TSTR + s16);
        asm volatile("cp.async.cg.shared.global [%0], [%1], 16;\n" ::"r"(sa), "l"(src)
                     : "memory");
    }
}

extern __shared__ float dyn_smem[];

__global__ void seg_kernel(const float* __restrict__ eh, const int* __restrict__ ss,
                           const int* __restrict__ se) {
    float* tile0 = dyn_smem;                     // 256*20 floats
    float* tile1 = dyn_smem + SEG_CH * TSTR;     // 256*20 floats
    float* ps = dyn_smem + 2 * SEG_CH * TSTR;    // 128*8 floats, [j][h]
    __shared__ float smax[HH], sinv[HH];
    __shared__ float wred[8][HH];

    int bid = blockIdx.x;
    int b = bid >> 6;
    int cs = blockIdx.y * SEG_CH;
    int st = ss[bid], en = se[bid];
    int tid = threadIdx.x, lane = tid & 31, wid = tid >> 5;
    const float* ebase = eh + (size_t)b * CC * TT_ + (size_t)cs * TT_;
    const float* abase = g_att + (size_t)b * HH * TT_;

    // phase 1: per-head max
    float mx[HH];
#pragma unroll
    for (int h = 0; h < HH; h++) mx[h] = -3.0e38f;
    for (int t = st + tid; t < en; t += 256) {
#pragma unroll
        for (int h = 0; h < HH; h++) mx[h] = fmaxf(mx[h], abase[(size_t)h * TT_ + t]);
    }
#pragma unroll
    for (int h = 0; h < HH; h++) mx[h] = warp_red_max(mx[h]);
    if (lane == 0)
        for (int h = 0; h < HH; h++) wred[wid][h] = mx[h];
    __syncthreads();
    if (tid < HH) {
        float v = wred[0][tid];
        for (int w = 1; w < 8; w++) v = fmaxf(v, wred[w][tid]);
        smax[tid] = v;
    }
    __syncthreads();

    // phase 2: per-head sum of exp
    float sm[HH];
#pragma unroll
    for (int h = 0; h < HH; h++) sm[h] = 0.f;
    for (int t = st + tid; t < en; t += 256) {
#pragma unroll
        for (int h = 0; h < HH; h++) sm[h] += __expf(abase[(size_t)h * TT_ + t] - smax[h]);
    }
#pragma unroll
    for (int h = 0; h < HH; h++) sm[h] = warp_red_sum(sm[h]);
    if (lane == 0)
        for (int h = 0; h < HH; h++) wred[wid][h] = sm[h];
    __syncthreads();
    if (tid < HH) {
        float v = 0.f;
        for (int w = 0; w < 8; w++) v += wred[w][tid];
        sinv[tid] = 1.f / v;
    }
    __syncthreads();

    // phase 3: thread owns channel c = cs + tid
    float acc[HH];
#pragma unroll
    for (int h = 0; h < HH; h++) acc[h] = 0.f;

    int t_lo = st & ~15;
    for (int mega = t_lo; mega < en; mega += MEGA) {
#pragma unroll
        for (int k = 0; k < 4; k++) {
            int idx = tid + k * 256;
            int j = idx >> 3, h = idx & 7;
            int t = mega + j;
            float v = 0.f;
            if (t >= st && t < en)
                v = __expf(abase[(size_t)h * TT_ + t] - smax[h]) * sinv[h];
            ps[idx] = v;
        }
        __syncthreads();

        int mend = min(mega + MEGA, en);
        int nch = (mend - mega + 15) >> 4;

        seg_prefetch(tile0, ebase, mega, tid);
        asm volatile("cp.async.commit_group;\n" ::: "memory");

        for (int ci = 0; ci < nch; ci++) {
            float* tb = (ci & 1) ? tile1 : tile0;
            float* tn = (ci & 1) ? tile0 : tile1;
            bool more = (ci + 1 < nch);
            if (more) {
                seg_prefetch(tn, ebase, mega + (ci + 1) * 16, tid);
                asm volatile("cp.async.commit_group;\n" ::: "memory");
                asm volatile("cp.async.wait_group 1;\n" ::: "memory");
            } else {
                asm volatile("cp.async.wait_group 0;\n" ::: "memory");
            }
            __syncthreads();

            const float* pj = ps + ci * 16 * 8;
            const float* r0 = tb + tid * TSTR;
#pragma unroll
            for (int jg = 0; jg < 4; jg++) {
                float4 e0 = *(const float4*)(r0 + jg * 4);
                float ea[4] = {e0.x, e0.y, e0.z, e0.w};
#pragma unroll
                for (int jj = 0; jj < 4; jj++) {
                    float4 pA = *(const float4*)(pj + (jg * 4 + jj) * 8);
                    float4 pB = *(const float4*)(pj + (jg * 4 + jj) * 8 + 4);
                    float p[8] = {pA.x, pA.y, pA.z, pA.w, pB.x, pB.y, pB.z, pB.w};
#pragma unroll
                    for (int h = 0; h < HH; h++) acc[h] = fmaf(p[h], ea[jj], acc[h]);
                }
            }
            __syncthreads();
        }
    }

    float* mo = g_m + (size_t)bid * HH * CC + cs + tid;
#pragma unroll
    for (int h = 0; h < HH; h++) mo[h * CC] = acc[h];
}

// ---------------------------------------------------------------------------
// tf32 tensor-core GEMM: C[m,n] = sum_k A[m,k]*B[n,k] (+ bias[n])
// Block: 64x64 tile, 256 threads (8 warps, warp tile 32m x 16n = 2x2 mma
// tiles of m16n8k8). K=512 in 16 chunks of 32, cp.async double-buffered.
// grid (16, 8): blockIdx.y selects head (gemm1) or n-block (gemm2) via
// caller-supplied pointer offsets a_off/b_off/c_off.
// ---------------------------------------------------------------------------
__device__ __forceinline__ uint32_t f2tf32(float v) {
    uint32_t r;
    asm("cvt.rna.tf32.f32 %0, %1;" : "=r"(r) : "f"(v));
    return r;
}

__device__ __forceinline__ void mma_tf32(float c[4], const uint32_t a[4],
                                         uint32_t b0, uint32_t b1) {
    asm volatile(
        "mma.sync.aligned.m16n8k8.row.col.f32.tf32.tf32.f32 "
        "{%0,%1,%2,%3}, {%4,%5,%6,%7}, {%8,%9}, {%0,%1,%2,%3};"
        : "+f"(c[0]), "+f"(c[1]), "+f"(c[2]), "+f"(c[3])
        : "r"(a[0]), "r"(a[1]), "r"(a[2]), "r"(a[3]), "r"(b0), "r"(b1));
}

__device__ __forceinline__ void gemm_prefetch(float (*dst)[GPAD], const float* src,
                                              int ld, int k0, int tid) {
#pragma unroll
    for (int i = 0; i < 2; i++) {
        int idx = tid + i * 256;          // 0..511 -> 64 rows x 8 float4
        int row = idx >> 3, c4 = (idx & 7) * 4;
        const float* s = src + (size_t)row * ld + k0 + c4;
        uint32_t sa = (uint32_t)__cvta_generic_to_shared(&dst[row][c4]);
        asm volatile("cp.async.cg.shared.global [%0], [%1], 16;\n" ::"r"(sa), "l"(s)
                     : "memory");
    }
}

__global__ void gemm_tf32_kernel(const float* __restrict__ A, const float* __restrict__ B,
                                 float* __restrict__ C, const float* __restrict__ bias,
                                 int lda, int a_off, int b_off, int c_off) {
    __shared__ float As[2][64][GPAD];
    __shared__ float Bs[2][64][GPAD];

    int tid = threadIdx.x, lane = tid & 31, wid = tid >> 5;
    int wm = wid >> 2, wn = wid & 3;   // warp tile: (wm*32, wn*16)
    int g = lane >> 2, l4 = lane & 3;

    int m0 = blockIdx.x * 64;
    const float* Ab = A + (size_t)blockIdx.y * a_off + (size_t)m0 * lda;
    const float* Bb = B + (size_t)blockIdx.y * b_off;
    float* Cb = C + (size_t)blockIdx.y * c_off;

    float acc[2][2][4];
#pragma unroll
    for (int mt = 0; mt < 2; mt++)
#pragma unroll
        for (int nt = 0; nt < 2; nt++)
#pragma unroll
            for (int i = 0; i < 4; i++) acc[mt][nt][i] = 0.f;

    gemm_prefetch(As[0], Ab, lda, 0, tid);
    gemm_prefetch(Bs[0], Bb, CC, 0, tid);
    asm volatile("cp.async.commit_group;\n" ::: "memory");

    for (int kc = 0; kc < 16; kc++) {
        int cur = kc & 1;
        if (kc < 15) {
            gemm_prefetch(As[cur ^ 1], Ab, lda, (kc + 1) * 32, tid);
            gemm_prefetch(Bs[cur ^ 1], Bb, CC, (kc + 1) * 32, tid);
            asm volatile("cp.async.commit_group;\n" ::: "memory");
            asm volatile("cp.async.wait_group 1;\n" ::: "memory");
        } else {
            asm volatile("cp.async.wait_group 0;\n" ::: "memory");
        }
        __syncthreads();

#pragma unroll
        for (int ks = 0; ks < 4; ks++) {
            int kb = ks * 8;
            uint32_t a[2][4], b[2][2];
#pragma unroll
            for (int mt = 0; mt < 2; mt++) {
                int r = wm * 32 + mt * 16 + g;
                a[mt][0] = f2tf32(As[cur][r][kb + l4]);
                a[mt][1] = f2tf32(As[cur][r + 8][kb + l4]);
                a[mt][2] = f2tf32(As[cur][r][kb + l4 + 4]);
                a[mt][3] = f2tf32(As[cur][r + 8][kb + l4 + 4]);
            }
#pragma unroll
            for (int nt = 0; nt < 2; nt++) {
                int n = wn * 16 + nt * 8 + g;
                b[nt][0] = f2tf32(Bs[cur][n][kb + l4]);
                b[nt][1] = f2tf32(Bs[cur][n][kb + l4 + 4]);
            }
#pragma unroll
            for (int mt = 0; mt < 2; mt++)
#pragma unroll
                for (int nt = 0; nt < 2; nt++)
                    mma_tf32(acc[mt][nt], a[mt], b[nt][0], b[nt][1]);
        }
        __syncthreads();
    }

    // epilogue: c0/c1 = row g, cols 2*l4, 2*l4+1 ; c2/c3 = row g+8
#pragma unroll
    for (int mt = 0; mt < 2; mt++) {
#pragma unroll
        for (int nt = 0; nt < 2; nt++) {
            int r = m0 + wm * 32 + mt * 16 + g;
            int cc = wn * 16 + nt * 8 + 2 * l4;
            float b0 = bias ? bias[(size_t)blockIdx.y * c_off % CC + cc] : 0.f;
            float b1 = bias ? bias[(size_t)blockIdx.y * c_off % CC + cc + 1] : 0.f;
            float2 v0 = make_float2(acc[mt][nt][0] + b0, acc[mt][nt][1] + b1);
            float2 v1 = make_float2(acc[mt][nt][2] + b0, acc[mt][nt][3] + b1);
            *(float2*)&Cb[(size_t)r * CC + cc] = v0;
            *(float2*)&Cb[(size_t)(r + 8) * CC + cc] = v1;
        }
    }
}

// ---------------------------------------------------------------------------
extern "C" void kernel_launch(void* const* d_in, const int* in_sizes, int n_in,
                              void* d_out, int out_size) {
    const float* x  = (const float*)d_in[0];
    const float* eh = (const float*)d_in[1];
    const int*   st = (const int*)d_in[2];
    const int*   en = (const int*)d_in[3];
    const float* Wq = (const float*)d_in[4];
    const float* bq = (const float*)d_in[5];
    const float* Wk = (const float*)d_in[6];
    /* d_in[7] = bk: constant per head in logits, cancels in softmax */
    const float* Wv = (const float*)d_in[8];
    const float* bv = (const float*)d_in[9];
    const float* Wp = (const float*)d_in[10];
    const float* bp = (const float*)d_in[11];
    float* out = (float*)d_out;

    cudaFuncSetAttribute(seg_kernel, cudaFuncAttributeMaxDynamicSharedMemorySize,
                         SEG_SMEM);

    float* d_m;    cudaGetSymbolAddress((void**)&d_m, g_m);
    float* d_tmp;  cudaGetSymbolAddress((void**)&d_tmp, g_tmp);
    float* d_cb;   cudaGetSymbolAddress((void**)&d_cb, g_cb);

    setup1_kernel<<<32, 512>>>(x, Wq, bq, Wp, bv, bp);
    setup2_kernel<<<HH, CC>>>(Wk);
    init_kernel<<<512, 256>>>();
    att_kernel<<<dim3(TT_ / 256, BB, CSPLIT), 256>>>(eh);
    seg_kernel<<<dim3(BB * SS, 2), 256, SEG_SMEM>>>(eh, st, en);
    // gemm1: per head h: g_tmp[:, h*64:(h+1)*64] = g_m[:, h, :] @ Wv_h^T
    gemm_tf32_kernel<<<dim3(16, HH), 256>>>(d_m, Wv, d_tmp, nullptr,
                                            HH * CC, CC, DD * CC, DD);
    // gemm2: out[:, ny*64:...] = g_tmp @ Wp_nblock^T + cb
    gemm_tf32_kernel<<<dim3(16, HH), 256>>>(d_tmp, Wp, out, d_cb,
                                            CC, 0, DD * CC, DD);
}

// round 8
// speedup vs baseline: 1.2008x; 1.0202x over previous
#include <cuda_runtime.h>
#include <cstdint>

// Problem constants
#define BB 16
#define SS 64
#define TT_ 4096
#define CC 512
#define HH 8
#define DD 64

#define TSTR 20      // seg tile row stride (floats)
#define MEGA 128     // t-positions of probabilities staged per outer iteration
#define SEG_CH 256   // channels per seg block (channel split x2)
#define SEG_SMEM ((2 * SEG_CH * TSTR + MEGA * HH) * 4)   // 45056 B

#define CSPLIT 4     // att channel split
#define CCH (CC / CSPLIT)   // 128 channels per att block

#define GPAD 36      // gemm smem row stride: conflict-free frag loads

// Scratch (device globals: allocation-free rule)
__device__ float g_q[CC];
__device__ float g_w[HH * CC];
__device__ float g_cb[CC];
__device__ float g_att[BB * HH * TT_];               // 2 MB
__device__ float g_m[(size_t)BB * SS * HH * CC];     // 16 MB
__device__ float g_tmp[BB * SS * CC];                // 2 MB

__device__ __forceinline__ float warp_red_max(float v) {
#pragma unroll
    for (int o = 16; o; o >>= 1) v = fmaxf(v, __shfl_xor_sync(0xffffffffu, v, o));
    return v;
}
__device__ __forceinline__ float warp_red_sum(float v) {
#pragma unroll
    for (int o = 16; o; o >>= 1) v += __shfl_xor_sync(0xffffffffu, v, o);
    return v;
}

// ---------------------------------------------------------------------------
// Setup stage 1: q = Wq@x + bq ; cb = bp + Wp@bv. grid 32 x 512.
// ---------------------------------------------------------------------------
__global__ void setup1_kernel(const float* __restrict__ x, const float* __restrict__ Wq,
                              const float* __restrict__ bq, const float* __restrict__ Wp,
                              const float* __restrict__ bv, const float* __restrict__ bp) {
    __shared__ float xs[CC], bvs[CC];
    int tid = threadIdx.x, lane = tid & 31, wid = tid >> 5;
    xs[tid] = x[tid];
    bvs[tid] = bv[tid];
    __syncthreads();

    int o = blockIdx.x * 16 + wid;
    {
        const float* r = Wq + (size_t)o * CC;
        float s = 0.f;
#pragma unroll 4
        for (int c = lane; c < CC; c += 32) s += r[c] * xs[c];
        s = warp_red_sum(s);
        if (lane == 0) g_q[o] = s + bq[o];
    }
    {
        const float* r = Wp + (size_t)o * CC;
        float s = 0.f;
#pragma unroll 4
        for (int c = lane; c < CC; c += 32) s += r[c] * bvs[c];
        s = warp_red_sum(s);
        if (lane == 0) g_cb[o] = s + bp[o];
    }
}

// ---------------------------------------------------------------------------
// Setup stage 2: w[h,c] = (1/8) * sum_d q[h*64+d] * Wk[h*64+d, c].  grid 8 x 512.
// ---------------------------------------------------------------------------
__global__ void setup2_kernel(const float* __restrict__ Wk) {
    __shared__ float qh[DD];
    int h = blockIdx.x, tid = threadIdx.x;
    if (tid < DD) qh[tid] = g_q[h * DD + tid];
    __syncthreads();
    const float* base = Wk + (size_t)h * DD * CC + tid;
    float s = 0.f;
#pragma unroll 8
    for (int d = 0; d < DD; d++) s = fmaf(qh[d], base[(size_t)d * CC], s);
    g_w[h * CC + tid] = 0.125f * s;
}

// ---------------------------------------------------------------------------
// Init: zero g_att (att atomic target). grid 512 x 256, float4 per thread.
// ---------------------------------------------------------------------------
__global__ void init_kernel() {
    int idx = blockIdx.x * 256 + threadIdx.x;
    ((float4*)g_att)[idx] = make_float4(0.f, 0.f, 0.f, 0.f);
}

// ---------------------------------------------------------------------------
// att (round-5 proven config): att[b,h,t] += w[h, cs:cs+128] . eh[b, cs:cs+128, t]
// grid (T/256, B, CSPLIT) = 1024 blocks x 256 threads, 1 t per thread.
// ---------------------------------------------------------------------------
__global__ void att_kernel(const float* __restrict__ eh) {
    __shared__ float ws[CCH][HH];  // [c][h], 4 KB
    int tid = threadIdx.x;
    int b = blockIdx.y;
    int cs = blockIdx.z * CCH;
    for (int idx = tid; idx < CCH * HH; idx += 256) {
        int c = idx >> 3, h = idx & 7;
        ws[c][h] = g_w[h * CC + cs + c];
    }
    __syncthreads();

    int t = blockIdx.x * 256 + tid;
    const float* e = eh + (size_t)b * CC * TT_ + (size_t)cs * TT_ + t;
    float acc[HH];
#pragma unroll
    for (int h = 0; h < HH; h++) acc[h] = 0.f;

#pragma unroll 8
    for (int c = 0; c < CCH; c++) {
        float v = e[(size_t)c * TT_];
        float4 w0 = *(const float4*)&ws[c][0];
        float4 w1 = *(const float4*)&ws[c][4];
        acc[0] = fmaf(w0.x, v, acc[0]);
        acc[1] = fmaf(w0.y, v, acc[1]);
        acc[2] = fmaf(w0.z, v, acc[2]);
        acc[3] = fmaf(w0.w, v, acc[3]);
        acc[4] = fmaf(w1.x, v, acc[4]);
        acc[5] = fmaf(w1.y, v, acc[5]);
        acc[6] = fmaf(w1.z, v, acc[6]);
        acc[7] = fmaf(w1.w, v, acc[7]);
    }
    float* ao = g_att + (size_t)b * HH * TT_ + t;
#pragma unroll
    for (int h = 0; h < HH; h++) atomicAdd(&ao[(size_t)h * TT_], acc[h]);
}

// ---------------------------------------------------------------------------
// seg: per (b,s,chalf) softmax then m[h, cs+c] = sum_t p[h,t]*eh[cs+c,t].
// grid (B*S, 2) x 256. cp.async double-buffered 256x16 tiles.
// Round-8 fix: ps staging reads att with t-fastest lane mapping (coalesced).
// ---------------------------------------------------------------------------
__device__ __forceinline__ void seg_prefetch(float* dst, const float* __restrict__ ebase,
                                             int t0, int tid) {
#pragma unroll
    for (int k = 0; k < 4; k++) {
        int idx = tid + k * 256;          // 0..1023
        int row = idx >> 2;               // channel 0..255
        int s16 = (idx & 3) * 4;          // float offset of 16B piece
        const float* src = ebase + (size_t)row * TT_ + t0 + s16;
        uint32_t sa = (uint32_t)__cvta_generic_to_shared(dst + row * TSTR + s16);
        asm volatile("cp.async.cg.shared.global [%0], [%1], 16;\n" ::"r"(sa), "l"(src)
                     : "memory");
    }
}

extern __shared__ float dyn_smem[];

__global__ void seg_kernel(const float* __restrict__ eh, const int* __restrict__ ss,
                           const int* __restrict__ se) {
    float* tile0 = dyn_smem;                     // 256*20 floats
    float* tile1 = dyn_smem + SEG_CH * TSTR;     // 256*20 floats
    float* ps = dyn_smem + 2 * SEG_CH * TSTR;    // 128*8 floats, [j][h]
    __shared__ float smax[HH], sinv[HH];
    __shared__ float wred[8][HH];

    int bid = blockIdx.x;
    int b = bid >> 6;
    int cs = blockIdx.y * SEG_CH;
    int st = ss[bid], en = se[bid];
    int tid = threadIdx.x, lane = tid & 31, wid = tid >> 5;
    const float* ebase = eh + (size_t)b * CC * TT_ + (size_t)cs * TT_;
    const float* abase = g_att + (size_t)b * HH * TT_;

    // phase 1: per-head max (t-fastest: coalesced)
    float mx[HH];
#pragma unroll
    for (int h = 0; h < HH; h++) mx[h] = -3.0e38f;
    for (int t = st + tid; t < en; t += 256) {
#pragma unroll
        for (int h = 0; h < HH; h++) mx[h] = fmaxf(mx[h], abase[(size_t)h * TT_ + t]);
    }
#pragma unroll
    for (int h = 0; h < HH; h++) mx[h] = warp_red_max(mx[h]);
    if (lane == 0)
        for (int h = 0; h < HH; h++) wred[wid][h] = mx[h];
    __syncthreads();
    if (tid < HH) {
        float v = wred[0][tid];
        for (int w = 1; w < 8; w++) v = fmaxf(v, wred[w][tid]);
        smax[tid] = v;
    }
    __syncthreads();

    // phase 2: per-head sum of exp (coalesced)
    float sm[HH];
#pragma unroll
    for (int h = 0; h < HH; h++) sm[h] = 0.f;
    for (int t = st + tid; t < en; t += 256) {
#pragma unroll
        for (int h = 0; h < HH; h++) sm[h] += __expf(abase[(size_t)h * TT_ + t] - smax[h]);
    }
#pragma unroll
    for (int h = 0; h < HH; h++) sm[h] = warp_red_sum(sm[h]);
    if (lane == 0)
        for (int h = 0; h < HH; h++) wred[wid][h] = sm[h];
    __syncthreads();
    if (tid < HH) {
        float v = 0.f;
        for (int w = 0; w < 8; w++) v += wred[w][tid];
        sinv[tid] = 1.f / v;
    }
    __syncthreads();

    // phase 3: thread owns channel c = cs + tid
    float acc[HH];
#pragma unroll
    for (int h = 0; h < HH; h++) acc[h] = 0.f;

    int t_lo = st & ~15;
    for (int mega = t_lo; mega < en; mega += MEGA) {
        // stage probabilities: lanes sweep adjacent t for one head -> coalesced
        // 128B global reads (was h-fastest: 32 sectors/warp, ~390MB overfetch).
#pragma unroll
        for (int k = 0; k < 4; k++) {
            int idx = tid + k * 256;          // 0..1023
            int h = idx >> 7, j = idx & 127;  // h fixed per half-warp group, j = t offset
            int t = mega + j;
            float v = 0.f;
            if (t >= st && t < en)
                v = __expf(abase[(size_t)h * TT_ + t] - smax[h]) * sinv[h];
            ps[j * 8 + h] = v;
        }
        __syncthreads();

        int mend = min(mega + MEGA, en);
        int nch = (mend - mega + 15) >> 4;

        seg_prefetch(tile0, ebase, mega, tid);
        asm volatile("cp.async.commit_group;\n" ::: "memory");

        for (int ci = 0; ci < nch; ci++) {
            float* tb = (ci & 1) ? tile1 : tile0;
            float* tn = (ci & 1) ? tile0 : tile1;
            bool more = (ci + 1 < nch);
            if (more) {
                seg_prefetch(tn, ebase, mega + (ci + 1) * 16, tid);
                asm volatile("cp.async.commit_group;\n" ::: "memory");
                asm volatile("cp.async.wait_group 1;\n" ::: "memory");
            } else {
                asm volatile("cp.async.wait_group 0;\n" ::: "memory");
            }
            __syncthreads();

            const float* pj = ps + ci * 16 * 8;
            const float* r0 = tb + tid * TSTR;
#pragma unroll
            for (int jg = 0; jg < 4; jg++) {
                float4 e0 = *(const float4*)(r0 + jg * 4);
                float ea[4] = {e0.x, e0.y, e0.z, e0.w};
#pragma unroll
                for (int jj = 0; jj < 4; jj++) {
                    float4 pA = *(const float4*)(pj + (jg * 4 + jj) * 8);
                    float4 pB = *(const float4*)(pj + (jg * 4 + jj) * 8 + 4);
                    float p[8] = {pA.x, pA.y, pA.z, pA.w, pB.x, pB.y, pB.z, pB.w};
#pragma unroll
                    for (int h = 0; h < HH; h++) acc[h] = fmaf(p[h], ea[jj], acc[h]);
                }
            }
            __syncthreads();
        }
    }

    float* mo = g_m + (size_t)bid * HH * CC + cs + tid;
#pragma unroll
    for (int h = 0; h < HH; h++) mo[h * CC] = acc[h];
}

// ---------------------------------------------------------------------------
// tf32 tensor-core GEMM: C[m,n] = sum_k A[m,k]*B[n,k] (+ bias[n])
// 64x64 tile, 256 threads (8 warps, warp tile 32x16 = 2x2 m16n8k8),
// K=512 in 16 chunks of 32, cp.async double-buffered.
// ---------------------------------------------------------------------------
__device__ __forceinline__ uint32_t f2tf32(float v) {
    uint32_t r;
    asm("cvt.rna.tf32.f32 %0, %1;" : "=r"(r) : "f"(v));
    return r;
}

__device__ __forceinline__ void mma_tf32(float c[4], const uint32_t a[4],
                                         uint32_t b0, uint32_t b1) {
    asm volatile(
        "mma.sync.aligned.m16n8k8.row.col.f32.tf32.tf32.f32 "
        "{%0,%1,%2,%3}, {%4,%5,%6,%7}, {%8,%9}, {%0,%1,%2,%3};"
        : "+f"(c[0]), "+f"(c[1]), "+f"(c[2]), "+f"(c[3])
        : "r"(a[0]), "r"(a[1]), "r"(a[2]), "r"(a[3]), "r"(b0), "r"(b1));
}

__device__ __forceinline__ void gemm_prefetch(float (*dst)[GPAD], const float* src,
                                              int ld, int k0, int tid) {
#pragma unroll
    for (int i = 0; i < 2; i++) {
        int idx = tid + i * 256;          // 0..511 -> 64 rows x 8 float4
        int row = idx >> 3, c4 = (idx & 7) * 4;
        const float* s = src + (size_t)row * ld + k0 + c4;
        uint32_t sa = (uint32_t)__cvta_generic_to_shared(&dst[row][c4]);
        asm volatile("cp.async.cg.shared.global [%0], [%1], 16;\n" ::"r"(sa), "l"(s)
                     : "memory");
    }
}

__global__ void gemm_tf32_kernel(const float* __restrict__ A, const float* __restrict__ B,
                                 float* __restrict__ C, const float* __restrict__ bias,
                                 int lda, int a_off, int b_off, int c_off) {
    __shared__ float As[2][64][GPAD];
    __shared__ float Bs[2][64][GPAD];

    int tid = threadIdx.x, lane = tid & 31, wid = tid >> 5;
    int wm = wid >> 2, wn = wid & 3;   // warp tile: (wm*32, wn*16)
    int g = lane >> 2, l4 = lane & 3;

    int m0 = blockIdx.x * 64;
    const float* Ab = A + (size_t)blockIdx.y * a_off + (size_t)m0 * lda;
    const float* Bb = B + (size_t)blockIdx.y * b_off;
    float* Cb = C + (size_t)blockIdx.y * c_off;

    float acc[2][2][4];
#pragma unroll
    for (int mt = 0; mt < 2; mt++)
#pragma unroll
        for (int nt = 0; nt < 2; nt++)
#pragma unroll
            for (int i = 0; i < 4; i++) acc[mt][nt][i] = 0.f;

    gemm_prefetch(As[0], Ab, lda, 0, tid);
    gemm_prefetch(Bs[0], Bb, CC, 0, tid);
    asm volatile("cp.async.commit_group;\n" ::: "memory");

    for (int kc = 0; kc < 16; kc++) {
        int cur = kc & 1;
        if (kc < 15) {
            gemm_prefetch(As[cur ^ 1], Ab, lda, (kc + 1) * 32, tid);
            gemm_prefetch(Bs[cur ^ 1], Bb, CC, (kc + 1) * 32, tid);
            asm volatile("cp.async.commit_group;\n" ::: "memory");
            asm volatile("cp.async.wait_group 1;\n" ::: "memory");
        } else {
            asm volatile("cp.async.wait_group 0;\n" ::: "memory");
        }
        __syncthreads();

#pragma unroll
        for (int ks = 0; ks < 4; ks++) {
            int kb = ks * 8;
            uint32_t a[2][4], b[2][2];
#pragma unroll
            for (int mt = 0; mt < 2; mt++) {
                int r = wm * 32 + mt * 16 + g;
                a[mt][0] = f2tf32(As[cur][r][kb + l4]);
                a[mt][1] = f2tf32(As[cur][r + 8][kb + l4]);
                a[mt][2] = f2tf32(As[cur][r][kb + l4 + 4]);
                a[mt][3] = f2tf32(As[cur][r + 8][kb + l4 + 4]);
            }
#pragma unroll
            for (int nt = 0; nt < 2; nt++) {
                int n = wn * 16 + nt * 8 + g;
                b[nt][0] = f2tf32(Bs[cur][n][kb + l4]);
                b[nt][1] = f2tf32(Bs[cur][n][kb + l4 + 4]);
            }
#pragma unroll
            for (int mt = 0; mt < 2; mt++)
#pragma unroll
                for (int nt = 0; nt < 2; nt++)
                    mma_tf32(acc[mt][nt], a[mt], b[nt][0], b[nt][1]);
        }
        __syncthreads();
    }

#pragma unroll
    for (int mt = 0; mt < 2; mt++) {
#pragma unroll
        for (int nt = 0; nt < 2; nt++) {
            int r = m0 + wm * 32 + mt * 16 + g;
            int cc = wn * 16 + nt * 8 + 2 * l4;
            float b0 = bias ? bias[(size_t)blockIdx.y * c_off % CC + cc] : 0.f;
            float b1 = bias ? bias[(size_t)blockIdx.y * c_off % CC + cc + 1] : 0.f;
            float2 v0 = make_float2(acc[mt][nt][0] + b0, acc[mt][nt][1] + b1);
            float2 v1 = make_float2(acc[mt][nt][2] + b0, acc[mt][nt][3] + b1);
            *(float2*)&Cb[(size_t)r * CC + cc] = v0;
            *(float2*)&Cb[(size_t)(r + 8) * CC + cc] = v1;
        }
    }
}

// ---------------------------------------------------------------------------
extern "C" void kernel_launch(void* const* d_in, const int* in_sizes, int n_in,
                              void* d_out, int out_size) {
    const float* x  = (const float*)d_in[0];
    const float* eh = (const float*)d_in[1];
    const int*   st = (const int*)d_in[2];
    const int*   en = (const int*)d_in[3];
    const float* Wq = (const float*)d_in[4];
    const float* bq = (const float*)d_in[5];
    const float* Wk = (const float*)d_in[6];
    /* d_in[7] = bk: constant per head in logits, cancels in softmax */
    const float* Wv = (const float*)d_in[8];
    const float* bv = (const float*)d_in[9];
    const float* Wp = (const float*)d_in[10];
    const float* bp = (const float*)d_in[11];
    float* out = (float*)d_out;

    cudaFuncSetAttribute(seg_kernel, cudaFuncAttributeMaxDynamicSharedMemorySize,
                         SEG_SMEM);

    float* d_m;    cudaGetSymbolAddress((void**)&d_m, g_m);
    float* d_tmp;  cudaGetSymbolAddress((void**)&d_tmp, g_tmp);
    float* d_cb;   cudaGetSymbolAddress((void**)&d_cb, g_cb);

    setup1_kernel<<<32, 512>>>(x, Wq, bq, Wp, bv, bp);
    setup2_kernel<<<HH, CC>>>(Wk);
    init_kernel<<<512, 256>>>();
    att_kernel<<<dim3(TT_ / 256, BB, CSPLIT), 256>>>(eh);
    seg_kernel<<<dim3(BB * SS, 2), 256, SEG_SMEM>>>(eh, st, en);
    // gemm1: per head h: g_tmp[:, h*64:(h+1)*64] = g_m[:, h, :] @ Wv_h^T
    gemm_tf32_kernel<<<dim3(16, HH), 256>>>(d_m, Wv, d_tmp, nullptr,
                                            HH * CC, CC, DD * CC, DD);
    // gemm2: out[:, ny*64:...] = g_tmp @ Wp_nblock^T + cb
    gemm_tf32_kernel<<<dim3(16, HH), 256>>>(d_tmp, Wp, out, d_cb,
                                            CC, 0, DD * CC, DD);
}

// round 9
// speedup vs baseline: 1.2133x; 1.0105x over previous
#include <cuda_runtime.h>
#include <cstdint>

// Problem constants
#define BB 16
#define SS 64
#define TT_ 4096
#define CC 512
#define HH 8
#define DD 64

#define TSTR 20      // seg tile row stride (floats): 80B rows, LDS.128 conflict-free
#define SEG_CH 256   // channels per seg block (chalf split x2)
#define RSPLIT 32    // t-range split per (b, chalf)
#define RNG (TT_ / RSPLIT)    // 128 t per block
#define NTILES (RNG / 16)     // 8 tiles of 16 t
#define SEG_SMEM ((2 * SEG_CH * TSTR + 16 * HH) * 4)   // 41472 B

#define CSPLIT 4     // att channel split
#define CCH (CC / CSPLIT)   // 128 channels per att block

#define GPAD 36      // gemm smem row stride: conflict-free frag loads

// Scratch (device globals: allocation-free rule)
__device__ float g_q[CC];
__device__ float g_w[HH * CC];
__device__ float g_cb[CC];
__device__ float g_att[BB * HH * TT_];               // 2 MB
__device__ float g_smax[BB * SS * HH];               // softmax stats tables
__device__ float g_sinv[BB * SS * HH];
__device__ float g_m[(size_t)BB * SS * HH * CC];     // 16 MB (atomic target)
__device__ float g_tmp[BB * SS * CC];                // 2 MB

__device__ __forceinline__ float warp_red_max(float v) {
#pragma unroll
    for (int o = 16; o; o >>= 1) v = fmaxf(v, __shfl_xor_sync(0xffffffffu, v, o));
    return v;
}
__device__ __forceinline__ float warp_red_sum(float v) {
#pragma unroll
    for (int o = 16; o; o >>= 1) v += __shfl_xor_sync(0xffffffffu, v, o);
    return v;
}

// ---------------------------------------------------------------------------
// Setup stage 1: q = Wq@x + bq ; cb = bp + Wp@bv. grid 32 x 512.
// ---------------------------------------------------------------------------
__global__ void setup1_kernel(const float* __restrict__ x, const float* __restrict__ Wq,
                              const float* __restrict__ bq, const float* __restrict__ Wp,
                              const float* __restrict__ bv, const float* __restrict__ bp) {
    __shared__ float xs[CC], bvs[CC];
    int tid = threadIdx.x, lane = tid & 31, wid = tid >> 5;
    xs[tid] = x[tid];
    bvs[tid] = bv[tid];
    __syncthreads();

    int o = blockIdx.x * 16 + wid;
    {
        const float* r = Wq + (size_t)o * CC;
        float s = 0.f;
#pragma unroll 4
        for (int c = lane; c < CC; c += 32) s += r[c] * xs[c];
        s = warp_red_sum(s);
        if (lane == 0) g_q[o] = s + bq[o];
    }
    {
        const float* r = Wp + (size_t)o * CC;
        float s = 0.f;
#pragma unroll 4
        for (int c = lane; c < CC; c += 32) s += r[c] * bvs[c];
        s = warp_red_sum(s);
        if (lane == 0) g_cb[o] = s + bp[o];
    }
}

// ---------------------------------------------------------------------------
// Setup stage 2: w[h,c] = (1/8) * sum_d q[h*64+d] * Wk[h*64+d, c].  grid 8 x 512.
// ---------------------------------------------------------------------------
__global__ void setup2_kernel(const float* __restrict__ Wk) {
    __shared__ float qh[DD];
    int h = blockIdx.x, tid = threadIdx.x;
    if (tid < DD) qh[tid] = g_q[h * DD + tid];
    __syncthreads();
    const float* base = Wk + (size_t)h * DD * CC + tid;
    float s = 0.f;
#pragma unroll 8
    for (int d = 0; d < DD; d++) s = fmaf(qh[d], base[(size_t)d * CC], s);
    g_w[h * CC + tid] = 0.125f * s;
}

// ---------------------------------------------------------------------------
// Init: zero g_m (seg atomic target) + g_att (att atomic target).
// grid 4096 x 256 (1M threads): g_m = 1M float4, g_att = 128K float4.
// ---------------------------------------------------------------------------
__global__ void init_kernel() {
    int idx = blockIdx.x * 256 + threadIdx.x;
    ((float4*)g_m)[idx] = make_float4(0.f, 0.f, 0.f, 0.f);
    if (idx < (BB * HH * TT_ / 4))
        ((float4*)g_att)[idx] = make_float4(0.f, 0.f, 0.f, 0.f);
}

// ---------------------------------------------------------------------------
// att (round-5 proven config): att[b,h,t] += w[h, cs:cs+128] . eh[b, cs:cs+128, t]
// grid (T/256, B, CSPLIT) = 1024 blocks x 256 threads, 1 t per thread.
// ---------------------------------------------------------------------------
__global__ void att_kernel(const float* __restrict__ eh) {
    __shared__ float ws[CCH][HH];  // [c][h], 4 KB
    int tid = threadIdx.x;
    int b = blockIdx.y;
    int cs = blockIdx.z * CCH;
    for (int idx = tid; idx < CCH * HH; idx += 256) {
        int c = idx >> 3, h = idx & 7;
        ws[c][h] = g_w[h * CC + cs + c];
    }
    __syncthreads();

    int t = blockIdx.x * 256 + tid;
    const float* e = eh + (size_t)b * CC * TT_ + (size_t)cs * TT_ + t;
    float acc[HH];
#pragma unroll
    for (int h = 0; h < HH; h++) acc[h] = 0.f;

#pragma unroll 8
    for (int c = 0; c < CCH; c++) {
        float v = e[(size_t)c * TT_];
        float4 w0 = *(const float4*)&ws[c][0];
        float4 w1 = *(const float4*)&ws[c][4];
        acc[0] = fmaf(w0.x, v, acc[0]);
        acc[1] = fmaf(w0.y, v, acc[1]);
        acc[2] = fmaf(w0.z, v, acc[2]);
        acc[3] = fmaf(w0.w, v, acc[3]);
        acc[4] = fmaf(w1.x, v, acc[4]);
        acc[5] = fmaf(w1.y, v, acc[5]);
        acc[6] = fmaf(w1.z, v, acc[6]);
        acc[7] = fmaf(w1.w, v, acc[7]);
    }
    float* ao = g_att + (size_t)b * HH * TT_ + t;
#pragma unroll
    for (int h = 0; h < HH; h++) atomicAdd(&ao[(size_t)h * TT_], acc[h]);
}

// ---------------------------------------------------------------------------
// stats: per (b,s) softmax max + inv-sum per head, ONCE (was duplicated per
// chalf inside seg). grid (B*S) x 256.
// ---------------------------------------------------------------------------
__global__ void stats_kernel(const int* __restrict__ ss, const int* __restrict__ se) {
    __shared__ float smax[HH];
    __shared__ float wred[8][HH];
    int bid = blockIdx.x;
    int b = bid >> 6;
    int st = ss[bid], en = se[bid];
    int tid = threadIdx.x, lane = tid & 31, wid = tid >> 5;
    const float* abase = g_att + (size_t)b * HH * TT_;

    float mx[HH];
#pragma unroll
    for (int h = 0; h < HH; h++) mx[h] = -3.0e38f;
    for (int t = st + tid; t < en; t += 256) {
#pragma unroll
        for (int h = 0; h < HH; h++) mx[h] = fmaxf(mx[h], abase[(size_t)h * TT_ + t]);
    }
#pragma unroll
    for (int h = 0; h < HH; h++) mx[h] = warp_red_max(mx[h]);
    if (lane == 0)
        for (int h = 0; h < HH; h++) wred[wid][h] = mx[h];
    __syncthreads();
    if (tid < HH) {
        float v = wred[0][tid];
        for (int w = 1; w < 8; w++) v = fmaxf(v, wred[w][tid]);
        smax[tid] = v;
    }
    __syncthreads();

    float sm[HH];
#pragma unroll
    for (int h = 0; h < HH; h++) sm[h] = 0.f;
    for (int t = st + tid; t < en; t += 256) {
#pragma unroll
        for (int h = 0; h < HH; h++) sm[h] += __expf(abase[(size_t)h * TT_ + t] - smax[h]);
    }
#pragma unroll
    for (int h = 0; h < HH; h++) sm[h] = warp_red_sum(sm[h]);
    if (lane == 0)
        for (int h = 0; h < HH; h++) wred[wid][h] = sm[h];
    __syncthreads();
    if (tid < HH) {
        float v = 0.f;
        for (int w = 0; w < 8; w++) v += wred[w][tid];
        g_smax[bid * HH + tid] = smax[tid];
        g_sinv[bid * HH + tid] = 1.f / v;
    }
}

// ---------------------------------------------------------------------------
// seg v4: uniform t-range blocks. grid (B, 2 chalf, RSPLIT) x 256.
// Block owns t in [rz*128, rz*128+128), walks 8 full 16-t tiles
// (cp.async double-buffered). Segments overlapping a tile form a contiguous
// s-range (starts AND ends are sorted). Register accumulators per current
// segment; flush via atomicAdd on segment change. No padding, no tail.
// ---------------------------------------------------------------------------
__device__ __forceinline__ void seg_prefetch(float* dst, const float* __restrict__ ebase,
                                             int t0, int tid) {
#pragma unroll
    for (int k = 0; k < 4; k++) {
        int idx = tid + k * 256;          // 0..1023
        int row = idx >> 2;               // channel 0..255
        int s16 = (idx & 3) * 4;          // float offset of 16B piece
        const float* src = ebase + (size_t)row * TT_ + t0 + s16;
        uint32_t sa = (uint32_t)__cvta_generic_to_shared(dst + row * TSTR + s16);
        asm volatile("cp.async.cg.shared.global [%0], [%1], 16;\n" ::"r"(sa), "l"(src)
                     : "memory");
    }
}

extern __shared__ float dyn_smem[];

__global__ void seg_kernel(const float* __restrict__ eh, const int* __restrict__ ss,
                           const int* __restrict__ se) {
    float* tile0 = dyn_smem;                     // 256*20 floats
    float* tile1 = dyn_smem + SEG_CH * TSTR;     // 256*20 floats
    float* ps = dyn_smem + 2 * SEG_CH * TSTR;    // 16*8 floats, [j][h]
    __shared__ int sst[SS], sen[SS];

    int b = blockIdx.x;
    int cs = blockIdx.y * SEG_CH;
    int t0base = blockIdx.z * RNG;
    int tid = threadIdx.x;

    if (tid < SS) {
        sst[tid] = ss[b * SS + tid];
        sen[tid] = se[b * SS + tid];
    }
    __syncthreads();

    // first segment whose end reaches into this range (ends sorted)
    int s = 0;
    while (s < SS && sen[s] <= t0base) s++;

    const float* ebase = eh + (size_t)b * CC * TT_ + (size_t)cs * TT_;
    const float* abase = g_att + (size_t)b * HH * TT_;

    float acc[HH];
#pragma unroll
    for (int h = 0; h < HH; h++) acc[h] = 0.f;
    int cur = -1;

    seg_prefetch(tile0, ebase, t0base, tid);
    asm volatile("cp.async.commit_group;\n" ::: "memory");

    for (int ti = 0; ti < NTILES; ti++) {
        int t0 = t0base + ti * 16;
        float* tb = (ti & 1) ? tile1 : tile0;
        float* tn = (ti & 1) ? tile0 : tile1;
        if (ti + 1 < NTILES) {
            seg_prefetch(tn, ebase, t0 + 16, tid);
            asm volatile("cp.async.commit_group;\n" ::: "memory");
            asm volatile("cp.async.wait_group 1;\n" ::: "memory");
        } else {
            asm volatile("cp.async.wait_group 0;\n" ::: "memory");
        }

        // segments overlapping [t0, t0+16): contiguous, uniform across threads
        int ls = s;
        while (ls < SS && sst[ls] < t0 + 16) {
            // stage ps for (segment ls, this tile)
            __syncthreads();   // prior ps reads + tile data visible
            if (tid < 16 * HH) {
                int h = tid >> 4, j = tid & 15;
                int t = t0 + j;
                int sb = (b * SS + ls) * HH + h;
                float v = 0.f;
                if (t >= sst[ls] && t < sen[ls])
                    v = __expf(abase[(size_t)h * TT_ + t] - g_smax[sb]) * g_sinv[sb];
                ps[j * HH + h] = v;
            }
            __syncthreads();

            if (ls != cur) {
                if (cur >= 0) {
                    float* mo = g_m + ((size_t)(b * SS + cur) * HH) * CC + cs + tid;
#pragma unroll
                    for (int h = 0; h < HH; h++) atomicAdd(&mo[(size_t)h * CC], acc[h]);
                }
#pragma unroll
                for (int h = 0; h < HH; h++) acc[h] = 0.f;
                cur = ls;
            }

            const float* r0 = tb + tid * TSTR;
#pragma unroll
            for (int jg = 0; jg < 4; jg++) {
                float4 e0 = *(const float4*)(r0 + jg * 4);
                float ea[4] = {e0.x, e0.y, e0.z, e0.w};
#pragma unroll
                for (int jj = 0; jj < 4; jj++) {
                    float4 pA = *(const float4*)(ps + (jg * 4 + jj) * 8);
                    float4 pB = *(const float4*)(ps + (jg * 4 + jj) * 8 + 4);
                    float p[8] = {pA.x, pA.y, pA.z, pA.w, pB.x, pB.y, pB.z, pB.w};
#pragma unroll
                    for (int h = 0; h < HH; h++) acc[h] = fmaf(p[h], ea[jj], acc[h]);
                }
            }
            ls++;
        }
        // drop segments that cannot reach the next tile (ends sorted)
        while (s < SS && sen[s] <= t0 + 16) s++;
        __syncthreads();   // all reads of tb done before it is refilled next iter
    }

    if (cur >= 0) {
        float* mo = g_m + ((size_t)(b * SS + cur) * HH) * CC + cs + tid;
#pragma unroll
        for (int h = 0; h < HH; h++) atomicAdd(&mo[(size_t)h * CC], acc[h]);
    }
}

// ---------------------------------------------------------------------------
// tf32 tensor-core GEMM: C[m,n] = sum_k A[m,k]*B[n,k] (+ bias[n])
// 64x64 tile, 256 threads (8 warps, warp tile 32x16 = 2x2 m16n8k8),
// K=512 in 16 chunks of 32, cp.async double-buffered.
// ---------------------------------------------------------------------------
__device__ __forceinline__ uint32_t f2tf32(float v) {
    uint32_t r;
    asm("cvt.rna.tf32.f32 %0, %1;" : "=r"(r) : "f"(v));
    return r;
}

__device__ __forceinline__ void mma_tf32(float c[4], const uint32_t a[4],
                                         uint32_t b0, uint32_t b1) {
    asm volatile(
        "mma.sync.aligned.m16n8k8.row.col.f32.tf32.tf32.f32 "
        "{%0,%1,%2,%3}, {%4,%5,%6,%7}, {%8,%9}, {%0,%1,%2,%3};"
        : "+f"(c[0]), "+f"(c[1]), "+f"(c[2]), "+f"(c[3])
        : "r"(a[0]), "r"(a[1]), "r"(a[2]), "r"(a[3]), "r"(b0), "r"(b1));
}

__device__ __forceinline__ void gemm_prefetch(float (*dst)[GPAD], const float* src,
                                              int ld, int k0, int tid) {
#pragma unroll
    for (int i = 0; i < 2; i++) {
        int idx = tid + i * 256;          // 0..511 -> 64 rows x 8 float4
        int row = idx >> 3, c4 = (idx & 7) * 4;
        const float* s = src + (size_t)row * ld + k0 + c4;
        uint32_t sa = (uint32_t)__cvta_generic_to_shared(&dst[row][c4]);
        asm volatile("cp.async.cg.shared.global [%0], [%1], 16;\n" ::"r"(sa), "l"(s)
                     : "memory");
    }
}

__global__ void gemm_tf32_kernel(const float* __restrict__ A, const float* __restrict__ B,
                                 float* __restrict__ C, const float* __restrict__ bias,
                                 int lda, int a_off, int b_off, int c_off) {
    __shared__ float As[2][64][GPAD];
    __shared__ float Bs[2][64][GPAD];

    int tid = threadIdx.x, lane = tid & 31, wid = tid >> 5;
    int wm = wid >> 2, wn = wid & 3;   // warp tile: (wm*32, wn*16)
    int g = lane >> 2, l4 = lane & 3;

    int m0 = blockIdx.x * 64;
    const float* Ab = A + (size_t)blockIdx.y * a_off + (size_t)m0 * lda;
    const float* Bb = B + (size_t)blockIdx.y * b_off;
    float* Cb = C + (size_t)blockIdx.y * c_off;

    float acc[2][2][4];
#pragma unroll
    for (int mt = 0; mt < 2; mt++)
#pragma unroll
        for (int nt = 0; nt < 2; nt++)
#pragma unroll
            for (int i = 0; i < 4; i++) acc[mt][nt][i] = 0.f;

    gemm_prefetch(As[0], Ab, lda, 0, tid);
    gemm_prefetch(Bs[0], Bb, CC, 0, tid);
    asm volatile("cp.async.commit_group;\n" ::: "memory");

    for (int kc = 0; kc < 16; kc++) {
        int cur = kc & 1;
        if (kc < 15) {
            gemm_prefetch(As[cur ^ 1], Ab, lda, (kc + 1) * 32, tid);
            gemm_prefetch(Bs[cur ^ 1], Bb, CC, (kc + 1) * 32, tid);
            asm volatile("cp.async.commit_group;\n" ::: "memory");
            asm volatile("cp.async.wait_group 1;\n" ::: "memory");
        } else {
            asm volatile("cp.async.wait_group 0;\n" ::: "memory");
        }
        __syncthreads();

#pragma unroll
        for (int ks = 0; ks < 4; ks++) {
            int kb = ks * 8;
            uint32_t a[2][4], b[2][2];
#pragma unroll
            for (int mt = 0; mt < 2; mt++) {
                int r = wm * 32 + mt * 16 + g;
                a[mt][0] = f2tf32(As[cur][r][kb + l4]);
                a[mt][1] = f2tf32(As[cur][r + 8][kb + l4]);
                a[mt][2] = f2tf32(As[cur][r][kb + l4 + 4]);
                a[mt][3] = f2tf32(As[cur][r + 8][kb + l4 + 4]);
            }
#pragma unroll
            for (int nt = 0; nt < 2; nt++) {
                int n = wn * 16 + nt * 8 + g;
                b[nt][0] = f2tf32(Bs[cur][n][kb + l4]);
                b[nt][1] = f2tf32(Bs[cur][n][kb + l4 + 4]);
            }
#pragma unroll
            for (int mt = 0; mt < 2; mt++)
#pragma unroll
                for (int nt = 0; nt < 2; nt++)
                    mma_tf32(acc[mt][nt], a[mt], b[nt][0], b[nt][1]);
        }
        __syncthreads();
    }

#pragma unroll
    for (int mt = 0; mt < 2; mt++) {
#pragma unroll
        for (int nt = 0; nt < 2; nt++) {
            int r = m0 + wm * 32 + mt * 16 + g;
            int cc = wn * 16 + nt * 8 + 2 * l4;
            float b0 = bias ? bias[(size_t)blockIdx.y * c_off % CC + cc] : 0.f;
            float b1 = bias ? bias[(size_t)blockIdx.y * c_off % CC + cc + 1] : 0.f;
            float2 v0 = make_float2(acc[mt][nt][0] + b0, acc[mt][nt][1] + b1);
            float2 v1 = make_float2(acc[mt][nt][2] + b0, acc[mt][nt][3] + b1);
            *(float2*)&Cb[(size_t)r * CC + cc] = v0;
            *(float2*)&Cb[(size_t)(r + 8) * CC + cc] = v1;
        }
    }
}

// ---------------------------------------------------------------------------
extern "C" void kernel_launch(void* const* d_in, const int* in_sizes, int n_in,
                              void* d_out, int out_size) {
    const float* x  = (const float*)d_in[0];
    const float* eh = (const float*)d_in[1];
    const int*   st = (const int*)d_in[2];
    const int*   en = (const int*)d_in[3];
    const float* Wq = (const float*)d_in[4];
    const float* bq = (const float*)d_in[5];
    const float* Wk = (const float*)d_in[6];
    /* d_in[7] = bk: constant per head in logits, cancels in softmax */
    const float* Wv = (const float*)d_in[8];
    const float* bv = (const float*)d_in[9];
    const float* Wp = (const float*)d_in[10];
    const float* bp = (const float*)d_in[11];
    float* out = (float*)d_out;

    cudaFuncSetAttribute(seg_kernel, cudaFuncAttributeMaxDynamicSharedMemorySize,
                         SEG_SMEM);

    float* d_m;    cudaGetSymbolAddress((void**)&d_m, g_m);
    float* d_tmp;  cudaGetSymbolAddress((void**)&d_tmp, g_tmp);
    float* d_cb;   cudaGetSymbolAddress((void**)&d_cb, g_cb);

    setup1_kernel<<<32, 512>>>(x, Wq, bq, Wp, bv, bp);
    setup2_kernel<<<HH, CC>>>(Wk);
    init_kernel<<<4096, 256>>>();
    att_kernel<<<dim3(TT_ / 256, BB, CSPLIT), 256>>>(eh);
    stats_kernel<<<BB * SS, 256>>>(st, en);
    seg_kernel<<<dim3(BB, 2, RSPLIT), 256, SEG_SMEM>>>(eh, st, en);
    // gemm1: per head h: g_tmp[:, h*64:(h+1)*64] = g_m[:, h, :] @ Wv_h^T
    gemm_tf32_kernel<<<dim3(16, HH), 256>>>(d_m, Wv, d_tmp, nullptr,
                                            HH * CC, CC, DD * CC, DD);
    // gemm2: out[:, ny*64:...] = g_tmp @ Wp_nblock^T + cb
    gemm_tf32_kernel<<<dim3(16, HH), 256>>>(d_tmp, Wp, out, d_cb,
                                            CC, 0, DD * CC, DD);
}